// round 13
// baseline (speedup 1.0000x reference)
#include <cuda_runtime.h>
#include <cstdint>

// Problem constants
#define BATCH 32
#define TT 512
#define NINP 128
#define NHID 1024
#define KTOT 1152
#define DT_C 0.042f
#define EPSH 512.0f               // HARMONIC = N_HID * 0.5

// Geometry: 128 CTAs = 32 col-groups x 4 batch-groups, 512 threads (16 warps)
#define NCTA 128
#define COLS 32
#define BPC  8
#define TPB  512
#define NW   16
#define KSL  72                   // k-rows per warp

#define BTH (BATCH * TT * NHID)

// SMEM (floats)
#define OFF_W   0
#define SZ_W    (KTOT * COLS)     // 36864, packed [k/4][c/2][8]
#define OFF_IN  (OFF_W + SZ_W)
#define SZ_IN   (KTOT * BPC)      // 9216, [k][8b]
#define OFF_RED (OFF_IN + SZ_IN)
#define SZ_RED  (NW * COLS * BPC) // 4096
#define SMEM_FLOATS (OFF_RED + SZ_RED)
#define SMEM_BYTES  (SMEM_FLOATS * 4)

// ---- device scratch ----
__device__ float g_xT2[4 * TT * NINP * BPC];   // [bg][t][i][8b]
__device__ float g_hyT2[2][4][NHID * BPC];     // [parity][bg][h][8b]
// one 128B line per flag: no false sharing between producers or pollers
__device__ __align__(128) unsigned g_flags[4][32][32];

typedef unsigned long long ull;

__device__ __forceinline__ void ffma2(ull& acc, ull a, ull b) {
    asm("fma.rn.f32x2 %0, %1, %2, %0;" : "+l"(acc) : "l"(a), "l"(b));
}
__device__ __forceinline__ ull pack2(float lo, float hi) {
    ull r; asm("mov.b64 %0, {%1, %2};" : "=l"(r) : "f"(lo), "f"(hi)); return r;
}
__device__ __forceinline__ unsigned ld_acq(const unsigned* p) {
    unsigned v;
    asm volatile("ld.global.acquire.gpu.u32 %0, [%1];" : "=r"(v) : "l"(p));
    return v;
}
__device__ __forceinline__ void st_rel(unsigned* p, unsigned v) {
    asm volatile("st.global.release.gpu.u32 [%0], %1;" :: "l"(p), "r"(v));
}

// one 4-k-row GEMM chunk (absolute chunk index ch)
#define GEMM_CHUNK(ch)                                                        \
    {                                                                         \
        float4 q0 = wqa[(ch) << 5];                                           \
        float4 q1 = wqa[((ch) << 5) + 1];                                     \
        const ulonglong2* hp = (const ulonglong2*)(in_s + ((ch) << 5) + (h << 2)); \
        ulonglong2 h0 = hp[0], h1 = hp[2], h2 = hp[4], h3 = hp[6];            \
        ull w2;                                                               \
        w2 = pack2(q0.x, q0.x); ffma2(A00, w2, h0.x); ffma2(A01, w2, h0.y);   \
        w2 = pack2(q0.y, q0.y); ffma2(A10, w2, h0.x); ffma2(A11, w2, h0.y);   \
        w2 = pack2(q0.z, q0.z); ffma2(A00, w2, h1.x); ffma2(A01, w2, h1.y);   \
        w2 = pack2(q0.w, q0.w); ffma2(A10, w2, h1.x); ffma2(A11, w2, h1.y);   \
        w2 = pack2(q1.x, q1.x); ffma2(A00, w2, h2.x); ffma2(A01, w2, h2.y);   \
        w2 = pack2(q1.y, q1.y); ffma2(A10, w2, h2.x); ffma2(A11, w2, h2.y);   \
        w2 = pack2(q1.z, q1.z); ffma2(A00, w2, h3.x); ffma2(A01, w2, h3.y);   \
        w2 = pack2(q1.w, q1.w); ffma2(A10, w2, h3.x); ffma2(A11, w2, h3.y);   \
    }

// ------------------------------------------------------------------
__global__ void k_init() {
    int idx = blockIdx.x * blockDim.x + threadIdx.x;
    int stride = gridDim.x * blockDim.x;
    for (int i = idx; i < 4 * 32 * 32; i += stride)
        (&g_flags[0][0][0])[i] = 0;
    for (int i = idx; i < 4 * NHID * BPC; i += stride)
        g_hyT2[0][0][i] = 0.0f;
}

__global__ void k_zero(float* __restrict__ p, int n4) {
    int idx = blockIdx.x * blockDim.x + threadIdx.x;
    int stride = gridDim.x * blockDim.x;
    float4 z = make_float4(0.f, 0.f, 0.f, 0.f);
    float4* p4 = reinterpret_cast<float4*>(p);
    for (int i = idx; i < n4; i += stride) p4[i] = z;
}

// x[b][t][i] -> g_xT2[bg][t][i][b&7]
__global__ void k_xpose(const float* __restrict__ x) {
    int idx = blockIdx.x * blockDim.x + threadIdx.x;
    int stride = gridDim.x * blockDim.x;
    const int N = 4 * TT * NINP * BPC;
    for (int o = idx; o < N; o += stride) {
        int blo = o & 7;
        int i = (o >> 3) & (NINP - 1);
        int t = (o >> 10) & (TT - 1);
        int bg = o >> 19;
        g_xT2[o] = x[((size_t)(bg * 8 + blo) * TT + t) * NINP + i];
    }
}

// ------------------------------------------------------------------
// persistent recurrent kernel: 128 CTAs x 512 threads
// per-warp producer-segment pipelining + conflict-free K reduction
// ------------------------------------------------------------------
__global__ void __launch_bounds__(TPB, 1) k_recur(
    const float* __restrict__ x2h,
    const float* __restrict__ h2h,
    const float* __restrict__ gamma,
    const float* __restrict__ eps,
    const float* __restrict__ bias,
    float* __restrict__ out)
{
    extern __shared__ float sm[];
    float* w_s  = sm + OFF_W;     // packed [kq][cp][r0c0,r0c1,...,r3c0,r3c1]
    float* in_s = sm + OFF_IN;    // [k][8b]
    float* red  = sm + OFF_RED;   // [w][256] in red-layout order

    const int tid  = threadIdx.x;
    const int wid  = tid >> 5;
    const int lane = tid & 31;
    const int cp   = lane >> 1;   // 0..15
    const int h    = lane & 1;    // 0..1
    const int cgrp = blockIdx.x >> 2;
    const int bg   = blockIdx.x & 3;
    const int cg0  = cgrp * COLS;
    const int b0g  = bg * BPC;
    const int kb   = wid * KSL;
    const int ke   = kb + KSL;

    // --- weights: coalesced global read -> packed SMEM ---
    for (int idx = tid; idx < KTOT * COLS; idx += TPB) {
        int k = idx >> 5;
        int c = idx & 31;
        float v = (k < NINP) ? x2h[(size_t)k * NHID + cg0 + c]
                             : h2h[(size_t)(k - NINP) * NHID + cg0 + c];
        w_s[((k >> 2) << 7) + ((c >> 1) << 3) + ((k & 3) << 1) + (c & 1)] = v;
    }

    // --- update params: thread tid<256 owns red-layout slot o = tid ---
    //     c = 2*((tid>>3)&15) + (tid>>7), b = tid&7  (bijection)
    const int ub2 = tid & 7;
    const int uc2 = 2 * ((tid >> 3) & 15) + ((tid >> 7) & 1);
    const int hg2 = cg0 + uc2;
    float hy_r = 0.f, hz_r = 0.f;
    float gam = 0.f, epc = 0.f, bi = 0.f;
    if (tid < 256) {
        gam = gamma[hg2];
        epc = eps[hg2] * EPSH;
        bi  = bias[hg2];
    }

    const float4* xs_all = (const float4*)(g_xT2 + (size_t)bg * (TT * NINP * BPC));
    const float4* wqa = (const float4*)w_s + (cp << 1);
    float4* dst4 = (float4*)in_s;
    float* rw = red + wid * (COLS * BPC);

    __syncthreads();

    for (int t = 0; t < TT; t++) {
        const int p = t & 1;

        ull A00 = 0, A01 = 0, A10 = 0, A11 = 0;
        int k0 = kb;

        // ---- x segment (no cross-CTA dependency) ----
        if (k0 < NINP) {
            int e = (ke < NINP) ? ke : NINP;
            const float4* xs = xs_all + (size_t)t * (NINP * BPC / 4);
            for (int i = k0 * 2 + lane; i < e * 2; i += 32)
                dst4[i] = __ldg(xs + i);
            __syncwarp();
            for (int ch = k0 >> 2; ch < (e >> 2); ch++) GEMM_CHUNK(ch);
            k0 = e;
        }

        // ---- hy segments, pipelined per producer block ----
        {
            const float4* hy4 = (const float4*)(&g_hyT2[p][bg][0]);
            while (k0 < ke) {
                int g = (k0 - NINP) >> 5;
                int e = NINP + ((g + 1) << 5);
                if (e > ke) e = ke;
                if (lane == 0) {
                    while (ld_acq(&g_flags[bg][g][0]) < (unsigned)t) { }
                }
                __syncwarp();
                for (int i = k0 * 2 + lane; i < e * 2; i += 32)
                    dst4[i] = __ldcg(hy4 + (i - NINP * 2));
                __syncwarp();
                for (int ch = k0 >> 2; ch < (e >> 2); ch++) GEMM_CHUNK(ch);
                k0 = e;
            }
        }

        // ---- red store: col 2cp at cp*8+4h, col 2cp+1 at 128+cp*8+4h ----
        {
            *(ulonglong2*)(rw + (cp << 3) + (h << 2))       = make_ulonglong2(A00, A01);
            *(ulonglong2*)(rw + 128 + (cp << 3) + (h << 2)) = make_ulonglong2(A10, A11);
        }
        __syncthreads();   // by here the CTA has observed ALL 32 flags >= t

        // ---- update: conflict-free coalesced reduction (red[w][tid]) ----
        if (tid < 256) {
            float pre = bi;
#pragma unroll
            for (int w = 0; w < NW; w++)
                pre += red[(w << 8) + tid];
            float drive = tanhf(pre);
            hz_r += DT_C * (drive - gam * hy_r - epc * hz_r);
            hy_r += DT_C * hz_r;

            __stcg(&g_hyT2[p ^ 1][bg][hg2 * BPC + ub2], hy_r);
        }
        __syncthreads();

        // ---- single-fence release to this CTA's private flag line ----
        if (tid == 0) {
            __threadfence();
            st_rel(&g_flags[bg][cgrp][0], (unsigned)(t + 1));
        }

        // out stores off the inter-CTA critical path
        if (tid < 256) {
            const size_t obase = (size_t)(b0g + ub2) * (TT * NHID) + (size_t)t * NHID + hg2;
            out[obase]       = hy_r;
            out[obase + BTH] = hz_r;
        }
    }
}

// ------------------------------------------------------------------
extern "C" void kernel_launch(void* const* d_in, const int* in_sizes, int n_in,
                              void* d_out, int out_size) {
    const float* x     = (const float*)d_in[0];
    const float* x2h   = (const float*)d_in[1];
    const float* h2h   = (const float*)d_in[2];
    const float* gamma = (const float*)d_in[3];
    const float* eps   = (const float*)d_in[4];
    const float* bias  = (const float*)d_in[5];
    float* out = (float*)d_out;

    cudaFuncSetAttribute(k_recur, cudaFuncAttributeMaxDynamicSharedMemorySize, SMEM_BYTES);

    k_init<<<64, 256>>>();
    k_xpose<<<512, 256>>>(x);
    // u and spike outputs are identically zero (u never leaves 0)
    k_zero<<<2048, 256>>>(out + (size_t)2 * BTH, (2 * BTH) / 4);
    k_recur<<<NCTA, TPB, SMEM_BYTES>>>(x2h, h2h, gamma, eps, bias, out);
}

// round 14
// speedup vs baseline: 1.7020x; 1.7020x over previous
#include <cuda_runtime.h>
#include <cstdint>

// Problem constants
#define BATCH 32
#define TT 512
#define NINP 128
#define NHID 1024
#define KTOT 1152
#define DT_C 0.042f
#define EPSH 512.0f               // HARMONIC = N_HID * 0.5

// Geometry: 128 CTAs = 32 col-groups x 4 batch-groups, 512 threads (16 warps)
#define NCTA 128
#define COLS 32
#define BPC  8
#define TPB  512
#define NW   16
#define KSL  72                   // k-rows per warp

#define BTH (BATCH * TT * NHID)

// SMEM (floats)
#define OFF_W   0
#define SZ_W    (KTOT * COLS)     // 36864, packed [k/4][c/2][8]
#define OFF_IN  (OFF_W + SZ_W)
#define SZ_IN   (KTOT * BPC)      // 9216, [k][8b]
#define OFF_RED (OFF_IN + SZ_IN)
#define SZ_RED  (NW * COLS * BPC) // 4096
#define SMEM_FLOATS (OFF_RED + SZ_RED)
#define SMEM_BYTES  (SMEM_FLOATS * 4)

// ---- device scratch ----
__device__ float g_xT2[4 * TT * NINP * BPC];   // [bg][t][i][8b]
__device__ float g_hyT2[2][4][NHID * BPC];     // [parity][bg][h][8b]
// one 128B line per flag: no false sharing between producers or pollers
__device__ __align__(128) unsigned g_flags[4][32][32];

typedef unsigned long long ull;

__device__ __forceinline__ void ffma2(ull& acc, ull a, ull b) {
    asm("fma.rn.f32x2 %0, %1, %2, %0;" : "+l"(acc) : "l"(a), "l"(b));
}
__device__ __forceinline__ ull pack2(float lo, float hi) {
    ull r; asm("mov.b64 %0, {%1, %2};" : "=l"(r) : "f"(lo), "f"(hi)); return r;
}
__device__ __forceinline__ unsigned ld_acq(const unsigned* p) {
    unsigned v;
    asm volatile("ld.global.acquire.gpu.u32 %0, [%1];" : "=r"(v) : "l"(p));
    return v;
}
__device__ __forceinline__ void st_rel(unsigned* p, unsigned v) {
    asm volatile("st.global.release.gpu.u32 [%0], %1;" :: "l"(p), "r"(v));
}

// ------------------------------------------------------------------
__global__ void k_init() {
    int idx = blockIdx.x * blockDim.x + threadIdx.x;
    int stride = gridDim.x * blockDim.x;
    for (int i = idx; i < 4 * 32 * 32; i += stride)
        (&g_flags[0][0][0])[i] = 0;
    for (int i = idx; i < 4 * NHID * BPC; i += stride)
        g_hyT2[0][0][i] = 0.0f;
}

__global__ void k_zero(float* __restrict__ p, int n4) {
    int idx = blockIdx.x * blockDim.x + threadIdx.x;
    int stride = gridDim.x * blockDim.x;
    float4 z = make_float4(0.f, 0.f, 0.f, 0.f);
    float4* p4 = reinterpret_cast<float4*>(p);
    for (int i = idx; i < n4; i += stride) p4[i] = z;
}

// x[b][t][i] -> g_xT2[bg][t][i][b&7]
__global__ void k_xpose(const float* __restrict__ x) {
    int idx = blockIdx.x * blockDim.x + threadIdx.x;
    int stride = gridDim.x * blockDim.x;
    const int N = 4 * TT * NINP * BPC;
    for (int o = idx; o < N; o += stride) {
        int blo = o & 7;
        int i = (o >> 3) & (NINP - 1);
        int t = (o >> 10) & (TT - 1);
        int bg = o >> 19;
        g_xT2[o] = x[((size_t)(bg * 8 + blo) * TT + t) * NINP + i];
    }
}

// ------------------------------------------------------------------
// persistent recurrent kernel: 128 CTAs x 512 threads
// R12 skeleton (fixed unrolled GEMM, fine-grained <=4-flag poll)
// + conflict-free coalesced K reduction (update thread owns red slot tid)
// ------------------------------------------------------------------
__global__ void __launch_bounds__(TPB, 1) k_recur(
    const float* __restrict__ x2h,
    const float* __restrict__ h2h,
    const float* __restrict__ gamma,
    const float* __restrict__ eps,
    const float* __restrict__ bias,
    float* __restrict__ out)
{
    extern __shared__ float sm[];
    float* w_s  = sm + OFF_W;     // packed [kq][cp][r0c0,r0c1,...,r3c0,r3c1]
    float* in_s = sm + OFF_IN;    // [k][8b]
    float* red  = sm + OFF_RED;   // [w][256] in red-layout order

    const int tid  = threadIdx.x;
    const int wid  = tid >> 5;
    const int lane = tid & 31;
    const int cp   = lane >> 1;   // 0..15
    const int h    = lane & 1;    // 0..1
    const int cgrp = blockIdx.x >> 2;
    const int bg   = blockIdx.x & 3;
    const int cg0  = cgrp * COLS;
    const int b0g  = bg * BPC;
    const int kb   = wid * KSL;

    // --- weights: coalesced global read -> packed SMEM ---
    for (int idx = tid; idx < KTOT * COLS; idx += TPB) {
        int k = idx >> 5;
        int c = idx & 31;
        float v = (k < NINP) ? x2h[(size_t)k * NHID + cg0 + c]
                             : h2h[(size_t)(k - NINP) * NHID + cg0 + c];
        w_s[((k >> 2) << 7) + ((c >> 1) << 3) + ((k & 3) << 1) + (c & 1)] = v;
    }

    // --- update params: thread tid<256 owns red-layout slot o = tid ---
    //     c = 2*((tid>>3)&15) + (tid>>7), b = tid&7  (bijection)
    const int ub2 = tid & 7;
    const int uc2 = 2 * ((tid >> 3) & 15) + ((tid >> 7) & 1);
    const int hg2 = cg0 + uc2;
    float hy_r = 0.f, hz_r = 0.f;
    float gam = 0.f, epc = 0.f, bi = 0.f;
    if (tid < 256) {
        gam = gamma[hg2];
        epc = eps[hg2] * EPSH;
        bi  = bias[hg2];
    }

    // --- this warp's producer flags (hy rows [kb-128, kb+72-128)) ---
    int p0 = 0, npf = 0;
    {
        int ke = kb + KSL;
        if (ke > NINP) {
            int h0 = ((kb > NINP) ? kb : NINP) - NINP;
            int h1 = ke - NINP - 1;
            p0 = h0 >> 5;
            npf = (h1 >> 5) - p0 + 1;   // <= 4
        }
    }
    const unsigned* myflag = &g_flags[bg][p0 + lane][0];  // lanes 0..npf-1 poll

    const float4* xs_all = (const float4*)(g_xT2 + (size_t)bg * (TT * NINP * BPC));
    const float4* wq = (const float4*)w_s + ((kb >> 2) << 5) + (cp << 1);
    float4* dst4 = (float4*)in_s;
    float* rw = red + wid * (COLS * BPC);

    __syncthreads();

    for (int t = 0; t < TT; t++) {
        const int p = t & 1;

        // ---- stage x rows (no cross-CTA dependency; in_s is warp-private) ----
        {
            const float4* xs = xs_all + (size_t)t * (NINP * BPC / 4);
#pragma unroll
            for (int i = lane; i < KSL * 2; i += 32) {
                int f4 = kb * 2 + i;
                if (f4 < NINP * 2) dst4[f4] = __ldg(xs + f4);
            }
        }

        // ---- fine-grained poll: only this warp's <=4 producers ----
        if (lane < npf) {
            const unsigned want = (unsigned)t;
            while (ld_acq(myflag) < want) { }
        }
        __syncwarp();

        // ---- stage hy rows (L2, cross-CTA coherent) ----
        {
            const float4* hy4 = (const float4*)(&g_hyT2[p][bg][0]);
#pragma unroll
            for (int i = lane; i < KSL * 2; i += 32) {
                int f4 = kb * 2 + i;
                if (f4 >= NINP * 2) dst4[f4] = __ldcg(hy4 + (f4 - NINP * 2));
            }
        }
        __syncwarp();

        // ---- GEMM: 18 fixed chunks x (4 k-rows, 2 cols/lane, 4 b/lane) ----
        ull A00 = 0, A01 = 0, A10 = 0, A11 = 0;
        const float* hb = in_s + kb * BPC + h * 4;
#pragma unroll
        for (int ch = 0; ch < KSL / 4; ch++) {
            float4 q0 = wq[ch * 32];
            float4 q1 = wq[ch * 32 + 1];
            const ulonglong2* hp = (const ulonglong2*)(hb + ch * 32);
            ulonglong2 h0 = hp[0];
            ulonglong2 h1 = hp[2];
            ulonglong2 h2 = hp[4];
            ulonglong2 h3 = hp[6];
            ull w2;
            w2 = pack2(q0.x, q0.x); ffma2(A00, w2, h0.x); ffma2(A01, w2, h0.y);
            w2 = pack2(q0.y, q0.y); ffma2(A10, w2, h0.x); ffma2(A11, w2, h0.y);
            w2 = pack2(q0.z, q0.z); ffma2(A00, w2, h1.x); ffma2(A01, w2, h1.y);
            w2 = pack2(q0.w, q0.w); ffma2(A10, w2, h1.x); ffma2(A11, w2, h1.y);
            w2 = pack2(q1.x, q1.x); ffma2(A00, w2, h2.x); ffma2(A01, w2, h2.y);
            w2 = pack2(q1.y, q1.y); ffma2(A10, w2, h2.x); ffma2(A11, w2, h2.y);
            w2 = pack2(q1.z, q1.z); ffma2(A00, w2, h3.x); ffma2(A01, w2, h3.y);
            w2 = pack2(q1.w, q1.w); ffma2(A10, w2, h3.x); ffma2(A11, w2, h3.y);
        }

        // ---- red store: col 2cp at cp*8+4h, col 2cp+1 at 128+cp*8+4h ----
        {
            *(ulonglong2*)(rw + (cp << 3) + (h << 2))       = make_ulonglong2(A00, A01);
            *(ulonglong2*)(rw + 128 + (cp << 3) + (h << 2)) = make_ulonglong2(A10, A11);
        }
        __syncthreads();   // by here the CTA has observed ALL 32 flags >= t

        // ---- update: conflict-free coalesced reduction (red[w][tid]) ----
        if (tid < 256) {
            float pre = bi;
#pragma unroll
            for (int w = 0; w < NW; w++)
                pre += red[(w << 8) + tid];
            float drive = tanhf(pre);
            hz_r += DT_C * (drive - gam * hy_r - epc * hz_r);
            hy_r += DT_C * hz_r;

            __stcg(&g_hyT2[p ^ 1][bg][hg2 * BPC + ub2], hy_r);
        }
        __syncthreads();

        // ---- single-fence release to this CTA's private flag line ----
        if (tid == 0) {
            __threadfence();
            st_rel(&g_flags[bg][cgrp][0], (unsigned)(t + 1));
        }

        // out stores off the inter-CTA critical path
        if (tid < 256) {
            const size_t obase = (size_t)(b0g + ub2) * (TT * NHID) + (size_t)t * NHID + hg2;
            out[obase]       = hy_r;
            out[obase + BTH] = hz_r;
        }
    }
}

// ------------------------------------------------------------------
extern "C" void kernel_launch(void* const* d_in, const int* in_sizes, int n_in,
                              void* d_out, int out_size) {
    const float* x     = (const float*)d_in[0];
    const float* x2h   = (const float*)d_in[1];
    const float* h2h   = (const float*)d_in[2];
    const float* gamma = (const float*)d_in[3];
    const float* eps   = (const float*)d_in[4];
    const float* bias  = (const float*)d_in[5];
    float* out = (float*)d_out;

    cudaFuncSetAttribute(k_recur, cudaFuncAttributeMaxDynamicSharedMemorySize, SMEM_BYTES);

    k_init<<<64, 256>>>();
    k_xpose<<<512, 256>>>(x);
    // u and spike outputs are identically zero (u never leaves 0)
    k_zero<<<2048, 256>>>(out + (size_t)2 * BTH, (2 * BTH) / 4);
    k_recur<<<NCTA, TPB, SMEM_BYTES>>>(x2h, h2h, gamma, eps, bias, out);
}